// round 2
// baseline (speedup 1.0000x reference)
#include <cuda_runtime.h>

// ============================================================================
// VQ-VAE quantizer:  z_e [131072, 64] fp32, emb [2048, 64] fp32
//   d2[n,k] = (||z_n||^2 - 2 z_n.e_k) + ||e_k||^2 ; idx = argmin_k
//   z_q_st  = z_e + (emb[idx] - z_e)
//   loss    = 0.25*mean(diff^2) + mean(diff^2)
// Output layout (float32): [ z_q_st (8388608) | loss (1) | idx (131072) ]
//
// Norms ||.||^2 are computed with the XLA-GPU row-reduction tree
// (per-warp shfl_down butterfly over 32 lanes, two warps combined by one add)
// to bitwise-match the reference's fp32 quantization -> identical argmin.
// ============================================================================

#define N_ROWS 131072
#define D      64
#define K      2048
#define TM     128      // rows per block
#define KC     128      // codes per chunk
#define NCHUNK (K / KC)
#define THREADS 256

// shared memory carve (bytes)
#define SM_ZZ   0                       // float2 [64][128]  = 65536
#define SM_E2   65536                   // float2 [64][66]   = 33792
#define SM_SE   (65536 + 33792)         // float  [2048]     = 8192
#define SM_SZ   (SM_SE + 8192)          // float  [128]      = 512
#define SM_BIDX (SM_SZ + 512)           // int    [128]      = 512
#define SM_LRED (SM_BIDX + 512)         // float  [8]        = 32
#define SMEM_BYTES (SM_LRED + 64)

__device__ float g_se[K];
__device__ float g_loss;

__device__ __forceinline__ void ffma2(unsigned long long& d,
                                      unsigned long long a,
                                      unsigned long long b) {
    asm("fma.rn.f32x2 %0, %1, %2, %0;" : "+l"(d) : "l"(a), "l"(b));
}

// XLA-GPU style warp-tree sum of 32 squared values (rounded mul, rounded adds,
// shfl_down pattern: l[t] += l[t+16], +8, +4, +2, +1), computed by one thread.
__device__ __forceinline__ float tree32_sq(const float* __restrict__ x, int stride) {
    float l[32];
    #pragma unroll
    for (int t = 0; t < 32; t++) {
        float v = x[t * stride];
        l[t] = __fmul_rn(v, v);
    }
    #pragma unroll
    for (int off = 16; off >= 1; off >>= 1)
        #pragma unroll
        for (int t = 0; t < 16; t++)
            if (t < off) l[t] = __fadd_rn(l[t], l[t + off]);
    return l[0];
}

__global__ void zero_kernel() { g_loss = 0.0f; }

__global__ void emb_norm_kernel(const float* __restrict__ emb) {
    int k = blockIdx.x * blockDim.x + threadIdx.x;
    if (k < K) {
        float a = tree32_sq(emb + k * D, 1);
        float b = tree32_sq(emb + k * D + 32, 1);
        g_se[k] = __fadd_rn(a, b);
    }
}

__global__ __launch_bounds__(THREADS)
void vq_main(const float* __restrict__ z_e,
             const float* __restrict__ emb,
             float* __restrict__ out,
             int write_idx) {
    extern __shared__ char smem[];
    float2* zz   = (float2*)(smem + SM_ZZ);    // [d][128] duplicated z values
    float2* e2   = (float2*)(smem + SM_E2);    // [d][66]  code-pair values
    float*  se   = (float*)(smem + SM_SE);
    float*  szs  = (float*)(smem + SM_SZ);
    int*    bidx = (int*)(smem + SM_BIDX);
    float*  lred = (float*)(smem + SM_LRED);

    const int tid = threadIdx.x;
    const int tx = tid & 15;    // code group (16)
    const int ty = tid >> 4;    // row group  (16)
    const int rowbase = blockIdx.x * TM;

    // ---- stage z tile: transpose to [d][r], duplicate each value ----
    for (int i = tid; i < TM * 16; i += THREADS) {
        int r = i >> 4, d4 = i & 15;
        float4 v = *(const float4*)(z_e + (rowbase + r) * D + d4 * 4);
        zz[(d4 * 4 + 0) * 128 + r] = make_float2(v.x, v.x);
        zz[(d4 * 4 + 1) * 128 + r] = make_float2(v.y, v.y);
        zz[(d4 * 4 + 2) * 128 + r] = make_float2(v.z, v.z);
        zz[(d4 * 4 + 3) * 128 + r] = make_float2(v.w, v.w);
    }
    // ---- stage codebook norms ----
    for (int i = tid; i < K; i += THREADS) se[i] = g_se[i];
    __syncthreads();

    // ---- per-row ||z||^2 via XLA-GPU reduction tree ----
    if (tid < TM) {
        // x[d] = zz[d*128 + tid].x ; stride between d's in floats = 256
        const float* xr = (const float*)(zz + tid);
        float a = tree32_sq(xr, 256);
        float b = tree32_sq(xr + 32 * 256, 256);
        szs[tid] = __fadd_rn(a, b);
    }
    __syncthreads();

    float szr[8];
    #pragma unroll
    for (int r = 0; r < 8; r++) szr[r] = szs[ty * 8 + r];

    float bestv[8];
    int   besti[8];
    #pragma unroll
    for (int r = 0; r < 8; r++) { bestv[r] = 3.4e38f; besti[r] = 0; }

    const unsigned long long* zp = (const unsigned long long*)zz + ty * 8;
    const unsigned long long* ep = (const unsigned long long*)e2 + tx * 4;

    for (int chunk = 0; chunk < NCHUNK; chunk++) {
        // ---- stage e chunk: pairs (c, c+1) transposed to [d][pair] ----
        for (int i = tid; i < (KC / 2) * 16; i += THREADS) {
            int c2 = i >> 4, d4 = i & 15;
            int c = chunk * KC + c2 * 2;
            float4 a = *(const float4*)(emb + c * D + d4 * 4);
            float4 b = *(const float4*)(emb + (c + 1) * D + d4 * 4);
            e2[(d4 * 4 + 0) * 66 + c2] = make_float2(a.x, b.x);
            e2[(d4 * 4 + 1) * 66 + c2] = make_float2(a.y, b.y);
            e2[(d4 * 4 + 2) * 66 + c2] = make_float2(a.z, b.z);
            e2[(d4 * 4 + 3) * 66 + c2] = make_float2(a.w, b.w);
        }
        __syncthreads();

        // ---- packed fp32 GEMM micro-tile: 8 rows x 4 code-pairs ----
        unsigned long long acc[8][4];
        #pragma unroll
        for (int r = 0; r < 8; r++)
            #pragma unroll
            for (int p = 0; p < 4; p++) acc[r][p] = 0ull;

        #pragma unroll 8
        for (int d = 0; d < D; d++) {
            ulonglong2 e01 = *(const ulonglong2*)(ep + d * 66);
            ulonglong2 e23 = *(const ulonglong2*)(ep + d * 66 + 2);
            #pragma unroll
            for (int rr = 0; rr < 4; rr++) {
                ulonglong2 zpr = *(const ulonglong2*)(zp + d * 128 + rr * 2);
                ffma2(acc[rr * 2 + 0][0], zpr.x, e01.x);
                ffma2(acc[rr * 2 + 0][1], zpr.x, e01.y);
                ffma2(acc[rr * 2 + 0][2], zpr.x, e23.x);
                ffma2(acc[rr * 2 + 0][3], zpr.x, e23.y);
                ffma2(acc[rr * 2 + 1][0], zpr.y, e01.x);
                ffma2(acc[rr * 2 + 1][1], zpr.y, e01.y);
                ffma2(acc[rr * 2 + 1][2], zpr.y, e23.x);
                ffma2(acc[rr * 2 + 1][3], zpr.y, e23.y);
            }
        }

        // ---- distances + running argmin (reference op order & rounding) ----
        const int cbase = chunk * KC + tx * 8;
        #pragma unroll
        for (int r = 0; r < 8; r++) {
            #pragma unroll
            for (int p = 0; p < 4; p++) {
                float2 dv = *(float2*)&acc[r][p];
                int c0 = cbase + 2 * p;
                float d20 = __fadd_rn(__fsub_rn(szr[r], __fmul_rn(2.0f, dv.x)), se[c0]);
                float d21 = __fadd_rn(__fsub_rn(szr[r], __fmul_rn(2.0f, dv.y)), se[c0 + 1]);
                if (d20 < bestv[r]) { bestv[r] = d20; besti[r] = c0; }
                if (d21 < bestv[r]) { bestv[r] = d21; besti[r] = c0 + 1; }
            }
        }
        __syncthreads();   // e2 WAR before next chunk restage
    }

    // ---- reduce argmin across the 16 code-group lanes (same half-warp) ----
    #pragma unroll
    for (int r = 0; r < 8; r++) {
        float v = bestv[r];
        int   bi = besti[r];
        #pragma unroll
        for (int m = 8; m >= 1; m >>= 1) {
            float ov = __shfl_xor_sync(0xffffffffu, v, m);
            int   oi = __shfl_xor_sync(0xffffffffu, bi, m);
            if (ov < v || (ov == v && oi < bi)) { v = ov; bi = oi; }
        }
        if (tx == 0) bidx[ty * 8 + r] = bi;
    }
    __syncthreads();

    // ---- gather + straight-through output + loss partial ----
    float lacc = 0.0f;
    for (int i = tid; i < TM * D; i += THREADS) {
        int r = i >> 6, d = i & 63;
        int bi = bidx[r];
        float q = emb[bi * D + d];
        float z = zz[d * 128 + r].x;
        float diff = __fsub_rn(q, z);                 // z_q - z_e
        out[(rowbase + r) * D + d] = __fadd_rn(z, diff);
        lacc = __fmaf_rn(diff, diff, lacc);
    }
    if (write_idx) {
        for (int i = tid; i < TM; i += THREADS)
            out[N_ROWS * D + 1 + rowbase + i] = (float)bidx[i];
    }

    // ---- block loss reduction -> global atomic ----
    #pragma unroll
    for (int m = 16; m >= 1; m >>= 1)
        lacc += __shfl_xor_sync(0xffffffffu, lacc, m);
    if ((tid & 31) == 0) lred[tid >> 5] = lacc;
    __syncthreads();
    if (tid == 0) {
        float s = 0.0f;
        #pragma unroll
        for (int w = 0; w < 8; w++) s += lred[w];
        atomicAdd(&g_loss, s);
    }
}

__global__ void finalize_kernel(float* __restrict__ out, int write_loss) {
    if (write_loss) {
        float m = g_loss / 8388608.0f;
        out[N_ROWS * D] = __fadd_rn(__fmul_rn(0.25f, m), m);
    }
}

extern "C" void kernel_launch(void* const* d_in, const int* in_sizes, int n_in,
                              void* d_out, int out_size) {
    const float* z_e = (const float*)d_in[0];
    const float* emb = (const float*)d_in[1];
    float* out = (float*)d_out;

    cudaFuncSetAttribute(vq_main, cudaFuncAttributeMaxDynamicSharedMemorySize,
                         SMEM_BYTES);

    int write_loss = (out_size > N_ROWS * D) ? 1 : 0;
    int write_idx  = (out_size >= N_ROWS * D + 1 + N_ROWS) ? 1 : 0;

    zero_kernel<<<1, 1>>>();
    emb_norm_kernel<<<K / 256, 256>>>(emb);
    vq_main<<<N_ROWS / TM, THREADS, SMEM_BYTES>>>(z_e, emb, out, write_idx);
    finalize_kernel<<<1, 1>>>(out, write_loss);
}